// round 15
// baseline (speedup 1.0000x reference)
#include <cuda_runtime.h>
#include <cuda_bf16.h>
#include <cstdint>
#include <math.h>

// ---------------- problem constants ----------------
#define BB 64
#define NTOK 1280
#define NQ 320
#define CIN 256
#define CKV 768
#define CQ 256
#define DHD 512
#define COUT 512
#define NH 8
#define KD 32
#define DV 64
#define EPSBN 1e-5f
#define SCALE_ATTN 0.17677669529663687f
#define LOG2E 1.4426950408889634f

#define M_KV (BB*NTOK)   // 81920
#define M_Q  (BB*NQ)     // 20480

// ---------------- device scratch ----------------
__device__ float g_xp[(size_t)M_KV * CIN];            // x: tf32, col-permuted
__device__ float g_sXsub[(size_t)M_Q * CIN];          // gathered x: tf32, col-permuted
__device__ float g_sOp[(size_t)M_Q * DHD];            // hswish(attn): tf32, col-permuted
__device__ float g_sP[(size_t)M_Q * COUT];
__device__ float g_Qt[(size_t)BB * NH * NQ * KD];     // raw fp32 Q head-major
__device__ float g_Kt[(size_t)BB * NH * NTOK * KD];   // tf32, col-permuted
__device__ float g_Vt[(size_t)BB * NH * NTOK * DV];   // tf32, key-pair-permuted [640][128]
__device__ float g_Wkvp[CKV * CIN];                   // tf32 permuted weights
__device__ float g_Wqp[CQ * CIN];
__device__ float g_Wpp[COUT * DHD];
__device__ float g_psumKV[640 * CKV], g_psqKV[640 * CKV];
__device__ float g_psumQ[160 * CQ],   g_psqQ[160 * CQ];
__device__ float g_psumP[160 * COUT], g_psqP[160 * COUT];
__device__ float g_aKV[CKV], g_shKV[CKV];
__device__ float g_aQ[CQ],  g_shQ[CQ];
__device__ float g_aP[COUT], g_shP[COUT];

// ---------------- helpers ----------------
__device__ __forceinline__ unsigned int f2tf(float f) {
    unsigned int r;
    asm("cvt.rna.tf32.f32 %0, %1;" : "=r"(r) : "f"(f));
    return r;
}
__device__ __forceinline__ float tf32f(float f) {
    unsigned int r;
    asm("cvt.rna.tf32.f32 %0, %1;" : "=r"(r) : "f"(f));
    return __uint_as_float(r);
}
__device__ __forceinline__ float ex2f(float x) {
    float r;
    asm("ex2.approx.f32 %0, %1;" : "=f"(r) : "f"(x));
    return r;
}
__device__ __forceinline__ int perm8i(int j) {   // k-pair (t,t+4) -> adjacent slots
    return (j < 4) ? 2 * j : 2 * (j - 4) + 1;
}
__device__ __forceinline__ void mma8(float* c, const unsigned int* a, const unsigned int* b) {
    asm volatile(
        "mma.sync.aligned.m16n8k8.row.col.f32.tf32.tf32.f32 "
        "{%0,%1,%2,%3}, {%4,%5,%6,%7}, {%8,%9}, {%0,%1,%2,%3};"
        : "+f"(c[0]), "+f"(c[1]), "+f"(c[2]), "+f"(c[3])
        : "r"(a[0]), "r"(a[1]), "r"(a[2]), "r"(a[3]), "r"(b[0]), "r"(b[1]));
}
__device__ __forceinline__ void cp_async16(unsigned int smem_addr, const void* gptr) {
    asm volatile("cp.async.cg.shared.global [%0], [%1], 16;\n"
                 :: "r"(smem_addr), "l"(gptr));
}

// permute one 8-col group: out4a=(i0,i4,i1,i5), out4b=(i2,i6,i3,i7), tf32-rounded
__device__ __forceinline__ void perm_group(const float4 a, const float4 b,
                                           float4& oa, float4& ob)
{
    oa = make_float4(tf32f(a.x), tf32f(b.x), tf32f(a.y), tf32f(b.y));
    ob = make_float4(tf32f(a.z), tf32f(b.z), tf32f(a.w), tf32f(b.w));
}

// ---------------- x -> tf32 permuted ----------------
__global__ void permute_x(const float* __restrict__ in, float* __restrict__ out)
{
    size_t g = (size_t)blockIdx.x * 256 + threadIdx.x;   // over M_KV*32 groups
    const float4* ip = (const float4*)in;
    float4* op = (float4*)out;
    float4 oa, ob;
    perm_group(ip[g * 2], ip[g * 2 + 1], oa, ob);
    op[g * 2] = oa; op[g * 2 + 1] = ob;
}

// ---------------- weight pre-permute ----------------
__global__ void permute_w(const float* __restrict__ in, float* __restrict__ out,
                          int K, int total)
{
    int i = blockIdx.x * 256 + threadIdx.x;
    if (i >= total) return;
    int row = i / K, k = i - row * K;
    int pos = (k & ~7) + perm8i(k & 7);
    out[row * K + pos] = tf32f(in[i]);
}

// ---------------- gather subsampled query tokens -> tf32 permuted ----------------
__global__ void gather_q_kernel(const float* __restrict__ x, float* __restrict__ xs)
{
    int idx = blockIdx.x * blockDim.x + threadIdx.x;   // over M_Q*32 groups
    int row = idx >> 5;
    int f   = idx & 31;          // 8-col group
    int b = row / NQ;
    int i = row - b * NQ;
    int src;
    if (i < 256) {
        int r = i >> 4, c = i & 15;
        src = (r * 2) * 32 + c * 2;
    } else {
        int j = i - 256;
        int r = j >> 3, c = j & 7;
        src = 1024 + (r * 2) * 16 + c * 2;
    }
    const float4* xp = (const float4*)x;
    float4* op = (float4*)xs;
    size_t sbase = ((size_t)b * NTOK + src) * 64 + f * 2;
    float4 oa, ob;
    perm_group(xp[sbase], xp[sbase + 1], oa, ob);
    op[(size_t)row * 64 + f * 2]     = oa;
    op[(size_t)row * 64 + f * 2 + 1] = ob;
}

// ---- tf32 GEMM v3: pre-permuted tf32 A and B, zero CVT, all LDS.64 ----
// mode 0: D0 row-major MxN (P proj)   mode 1: K perm-tf32 + V pair-perm tf32
// mode 2: Q raw fp32 head-major
#define GSTR 36
#define G_TILE (128*GSTR)              // 4608
#define G_SMEMF (4*G_TILE)             // 18432 floats = 73728 B

__global__ __launch_bounds__(256, 2)
void gemm_tf32_stats(const float* __restrict__ Ap, const float* __restrict__ Bp,
                     float* __restrict__ D0, float* __restrict__ D1,
                     float* __restrict__ psum, float* __restrict__ psq,
                     int M, int N, int K, int mode)
{
    extern __shared__ float smf[];
    unsigned int smb = (unsigned int)__cvta_generic_to_shared(smf);

    int tid = threadIdx.x;
    int bm = blockIdx.y * 128, bn = blockIdx.x * 128;
    int wid = tid >> 5, lane = tid & 31;
    int wm = (wid >> 1) << 5;
    int wn = (wid & 1) << 6;
    int gid = lane >> 2, tg = lane & 3;

    float acc[2][8][4];
#pragma unroll
    for (int im = 0; im < 2; im++)
#pragma unroll
        for (int j = 0; j < 8; j++)
#pragma unroll
            for (int r = 0; r < 4; r++) acc[im][j][r] = 0.f;

    int nch = K >> 5;
    int srow = tid >> 3, sc4 = tid & 7;

#pragma unroll
    for (int i = 0; i < 4; i++) {
        int row = srow + i * 32;
        cp_async16(smb + (unsigned int)((row * GSTR + sc4 * 4) << 2),
                   Ap + (size_t)(bm + row) * K + sc4 * 4);
        cp_async16(smb + (unsigned int)((2 * G_TILE + row * GSTR + sc4 * 4) << 2),
                   Bp + (size_t)(bn + row) * K + sc4 * 4);
    }
    asm volatile("cp.async.commit_group;\n");

    for (int c = 0; c < nch; c++) {
        if (c + 1 < nch) {
            int k0 = (c + 1) << 5;
            unsigned int aoff = ((c + 1) & 1) ? G_TILE : 0u;
            unsigned int boff = 2 * G_TILE + aoff;
#pragma unroll
            for (int i = 0; i < 4; i++) {
                int row = srow + i * 32;
                cp_async16(smb + (unsigned int)((aoff + row * GSTR + sc4 * 4) << 2),
                           Ap + (size_t)(bm + row) * K + k0 + sc4 * 4);
                cp_async16(smb + (unsigned int)((boff + row * GSTR + sc4 * 4) << 2),
                           Bp + (size_t)(bn + row) * K + k0 + sc4 * 4);
            }
            asm volatile("cp.async.commit_group;\n");
            asm volatile("cp.async.wait_group 1;\n");
        } else {
            asm volatile("cp.async.wait_group 0;\n");
        }
        __syncthreads();

        const float* Ar = smf + (c & 1) * G_TILE;
        const float* Br = smf + 2 * G_TILE + (c & 1) * G_TILE;

#pragma unroll
        for (int s = 0; s < 4; s++) {
            int kk = s * 8;
            unsigned int af[2][4], bf[8][2];
#pragma unroll
            for (int im = 0; im < 2; im++) {
                float2 v0 = *(const float2*)(Ar + (wm + im * 16 + gid) * GSTR + kk + tg * 2);
                float2 v1 = *(const float2*)(Ar + (wm + im * 16 + gid + 8) * GSTR + kk + tg * 2);
                af[im][0] = __float_as_uint(v0.x);
                af[im][1] = __float_as_uint(v1.x);
                af[im][2] = __float_as_uint(v0.y);
                af[im][3] = __float_as_uint(v1.y);
            }
#pragma unroll
            for (int j = 0; j < 8; j++) {
                float2 v = *(const float2*)(Br + (wn + j * 8 + gid) * GSTR + kk + tg * 2);
                bf[j][0] = __float_as_uint(v.x);
                bf[j][1] = __float_as_uint(v.y);
            }
#pragma unroll
            for (int im = 0; im < 2; im++)
#pragma unroll
                for (int j = 0; j < 8; j++)
                    mma8(acc[im][j], af[im], bf[j]);
        }
        __syncthreads();
    }

    // ---------- stores ----------
#pragma unroll
    for (int im = 0; im < 2; im++) {
        int r0 = bm + wm + im * 16 + gid;
#pragma unroll
        for (int j = 0; j < 8; j++) {
            int c0 = bn + wn + j * 8 + tg * 2;
            if (mode == 0) {
                *(float2*)&D0[(size_t)r0 * N + c0] = make_float2(acc[im][j][0], acc[im][j][1]);
                *(float2*)&D0[(size_t)(r0 + 8) * N + c0] = make_float2(acc[im][j][2], acc[im][j][3]);
            } else if (mode == 1) {
                int h = c0 / 96, jj = c0 % 96;
                int b = r0 / NTOK, n0 = r0 - b * NTOK;
                if (jj < 32) {
                    int pe = (jj & ~7) + perm8i(jj & 7);
                    int po = (jj & ~7) + perm8i((jj & 7) + 1);
                    float* kp = D0 + ((size_t)(b * NH + h) * NTOK + n0) * KD;
                    kp[pe] = tf32f(acc[im][j][0]);
                    kp[po] = tf32f(acc[im][j][1]);
                    kp[8 * KD + pe] = tf32f(acc[im][j][2]);
                    kp[8 * KD + po] = tf32f(acc[im][j][3]);
                } else {
                    int d = jj - 32;
                    int rw = ((n0 & ~7) >> 1) + (n0 & 3);
                    int s2 = (n0 >> 2) & 1;
                    float* vp = D1 + (size_t)(b * NH + h) * NTOK * DV + (size_t)rw * 128;
                    vp[d * 2 + s2]     = tf32f(acc[im][j][0]);
                    vp[d * 2 + 2 + s2] = tf32f(acc[im][j][1]);
                    vp[4 * 128 + d * 2 + s2]     = tf32f(acc[im][j][2]);
                    vp[4 * 128 + d * 2 + 2 + s2] = tf32f(acc[im][j][3]);
                }
            } else {
                int h = c0 >> 5, jj = c0 & 31;
                int b0 = r0 / NQ, q0r = r0 - b0 * NQ;
                int r1 = r0 + 8;
                int b1 = r1 / NQ, q1r = r1 - b1 * NQ;
                *(float2*)&D0[((size_t)(b0 * NH + h) * NQ + q0r) * KD + jj] =
                    make_float2(acc[im][j][0], acc[im][j][1]);
                *(float2*)&D0[((size_t)(b1 * NH + h) * NQ + q1r) * KD + jj] =
                    make_float2(acc[im][j][2], acc[im][j][3]);
            }
        }
    }

    // ---------- fused BN column stats ----------
    float cs[16], cq[16];
#pragma unroll
    for (int j = 0; j < 8; j++) {
#pragma unroll
        for (int r = 0; r < 2; r++) {
            float s = 0.f, q2 = 0.f;
#pragma unroll
            for (int im = 0; im < 2; im++) {
                float x0 = acc[im][j][r];
                float x1 = acc[im][j][r + 2];
                s += x0 + x1;
                q2 += x0 * x0 + x1 * x1;
            }
            cs[j * 2 + r] = s;
            cq[j * 2 + r] = q2;
        }
    }
#pragma unroll
    for (int m = 4; m <= 16; m <<= 1) {
#pragma unroll
        for (int i = 0; i < 16; i++) {
            cs[i] += __shfl_xor_sync(0xffffffffu, cs[i], m);
            cq[i] += __shfl_xor_sync(0xffffffffu, cq[i], m);
        }
    }
    float* st = smf;
    if (gid == 0) {
        int wmi = wid >> 1;
#pragma unroll
        for (int i = 0; i < 16; i++) {
            int cl = wn + (i >> 1) * 8 + tg * 2 + (i & 1);
            st[wmi * 128 + cl] = cs[i];
            st[512 + wmi * 128 + cl] = cq[i];
        }
    }
    __syncthreads();
    if (tid < 128) {
        float s = st[tid] + st[128 + tid] + st[256 + tid] + st[384 + tid];
        float q2 = st[512 + tid] + st[640 + tid] + st[768 + tid] + st[896 + tid];
        psum[(size_t)blockIdx.y * N + bn + tid] = s;
        psq [(size_t)blockIdx.y * N + bn + tid] = q2;
    }
}

// ---------------- BN finalize ----------------
__global__ void bn_finalize2(const float* __restrict__ psum, const float* __restrict__ psq,
                             const float* __restrict__ g, const float* __restrict__ bta,
                             int C, int R, float invM,
                             float* __restrict__ a, float* __restrict__ sh)
{
    int tx = threadIdx.x, ty = threadIdx.y;
    int col = blockIdx.x * 32 + tx;
    float s = 0.f, q2 = 0.f;
    for (int r = ty; r < R; r += 16) {
        s  += psum[(size_t)r * C + col];
        q2 += psq[(size_t)r * C + col];
    }
    __shared__ float ss[16][32], sq[16][32];
    ss[ty][tx] = s; sq[ty][tx] = q2;
    __syncthreads();
    if (ty == 0) {
        float ts = 0.f, tq = 0.f;
#pragma unroll
        for (int y = 0; y < 16; y++) { ts += ss[y][tx]; tq += sq[y][tx]; }
        float mean = ts * invM;
        float var = tq * invM - mean * mean;
        float aa = g[col] * rsqrtf(var + EPSBN);
        a[col] = aa;
        sh[col] = bta[col] - mean * aa;
    }
}

// ---------------- tensor-core flash attention ----------------
#define A_KSTR 36
#define A_VSTR 144
#define A_PSTR 68
#define A_KT (64*A_KSTR)                 // 2304
#define A_VT (32*A_VSTR)                 // 4608
#define A_BUF (A_KT + A_VT)              // 6912
#define A_POFF (2*A_BUF)                 // 13824
#define A_TOTALF (A_POFF + 4*16*A_PSTR)  // 18176 floats = 72704 B

__device__ __forceinline__ void stage_tile(unsigned int smem_bytes,
                                           const float* __restrict__ Kg,
                                           const float* __restrict__ Vg,
                                           int kt, int tid)
{
    const float4* Ks = (const float4*)(Kg + (size_t)kt * 64 * KD);
    const float4* Vs = (const float4*)(Vg + (size_t)kt * 64 * DV);
#pragma unroll
    for (int i = 0; i < 4; i++) {
        int idx = i * 128 + tid; int r = idx >> 3, f = idx & 7;
        cp_async16(smem_bytes + (unsigned int)((r * A_KSTR + f * 4) << 2), Ks + r * 8 + f);
    }
#pragma unroll
    for (int i = 0; i < 8; i++) {
        int idx = i * 128 + tid; int r = idx >> 5, f = idx & 31;
        cp_async16(smem_bytes + (unsigned int)((A_KT + r * A_VSTR + f * 4) << 2),
                   Vs + r * 32 + f);
    }
}

__device__ __forceinline__ float hswish(float x) {
    return x * fminf(fmaxf(x + 3.f, 0.f), 6.f) * (1.f / 6.f);
}

__global__ __launch_bounds__(128)
void attn_tc(const float* __restrict__ Qt, const float* __restrict__ Kt,
             const float* __restrict__ Vt,
             const float* __restrict__ aQ, const float* __restrict__ shQ,
             const float* __restrict__ aKV, const float* __restrict__ shKV,
             float* __restrict__ O)
{
    extern __shared__ float smf[];
    int tid  = threadIdx.x;
    int warp = tid >> 5, lane = tid & 31;
    int gid = lane >> 2, tg = lane & 3;
    int qt = blockIdx.x, h = blockIdx.y, b = blockIdx.z;
    int bh = b * NH + h;

    const float* Kg = Kt + (size_t)bh * NTOK * KD;
    const float* Vg = Vt + (size_t)bh * NTOK * DV;
    unsigned int smb = (unsigned int)__cvta_generic_to_shared(smf);
    float* Pw = smf + A_POFF + warp * (16 * A_PSTR);

    int q0 = qt * 64 + warp * 16;
    const float* Qg  = Qt + ((size_t)bh * NQ + q0) * KD;
    const float* aQh = aQ + h * KD;
    const float* sQh = shQ + h * KD;
    const float* aKh = aKV + h * 96;
    const float SC = SCALE_ATTN * LOG2E;
    unsigned int qa[4][4];
#pragma unroll
    for (int kc = 0; kc < 4; kc++) {
        int c0 = kc * 8 + tg, c1 = c0 + 4;
        float m0 = __ldg(aQh + c0) * __ldg(aKh + c0) * SC;
        float o0 = __ldg(sQh + c0) * __ldg(aKh + c0) * SC;
        float m1 = __ldg(aQh + c1) * __ldg(aKh + c1) * SC;
        float o1 = __ldg(sQh + c1) * __ldg(aKh + c1) * SC;
        qa[kc][0] = f2tf(__ldg(Qg + gid * KD + c0)       * m0 + o0);
        qa[kc][1] = f2tf(__ldg(Qg + (gid + 8) * KD + c0) * m0 + o0);
        qa[kc][2] = f2tf(__ldg(Qg + gid * KD + c1)       * m1 + o1);
        qa[kc][3] = f2tf(__ldg(Qg + (gid + 8) * KD + c1) * m1 + o1);
    }

    float acc[8][4];
#pragma unroll
    for (int nt = 0; nt < 8; nt++)
#pragma unroll
        for (int r = 0; r < 4; r++) acc[nt][r] = 0.f;
    float l0 = 0.f, l1 = 0.f;

    int pe = perm8i(2 * tg), po = perm8i(2 * tg + 1);

    stage_tile(smb, Kg, Vg, 0, tid);
    asm volatile("cp.async.commit_group;\n");

    const int NKT = NTOK / 64;
    for (int kt = 0; kt < NKT; kt++) {
        if (kt + 1 < NKT) {
            stage_tile(smb + ((kt + 1) & 1) * A_BUF * 4, Kg, Vg, kt + 1, tid);
            asm volatile("cp.async.commit_group;\n");
            asm volatile("cp.async.wait_group 1;\n");
        } else {
            asm volatile("cp.async.wait_group 0;\n");
        }
        __syncthreads();

        const float* Ksm = smf + (kt & 1) * A_BUF;
        const float* Vsm = Ksm + A_KT;

#pragma unroll
        for (int nt = 0; nt < 8; nt++) {
            float c[4] = {0.f, 0.f, 0.f, 0.f};
#pragma unroll
            for (int kc = 0; kc < 4; kc++) {
                float2 kv = *(const float2*)(Ksm + (nt * 8 + gid) * A_KSTR + kc * 8 + tg * 2);
                unsigned int bb[2] = { __float_as_uint(kv.x), __float_as_uint(kv.y) };
                mma8(c, qa[kc], bb);
            }
            float p0 = ex2f(c[0]), p1 = ex2f(c[1]);
            float p2 = ex2f(c[2]), p3 = ex2f(c[3]);
            l0 += p0 + p1;
            l1 += p2 + p3;
            float* pr0 = Pw + gid * A_PSTR + nt * 8;
            float* pr1 = Pw + (gid + 8) * A_PSTR + nt * 8;
            pr0[pe] = tf32f(p0); pr0[po] = tf32f(p1);
            pr1[pe] = tf32f(p2); pr1[po] = tf32f(p3);
        }
        __syncwarp();

#pragma unroll
        for (int kc = 0; kc < 8; kc++) {
            float2 pv0 = *(const float2*)(Pw + gid * A_PSTR + kc * 8 + tg * 2);
            float2 pv1 = *(const float2*)(Pw + (gid + 8) * A_PSTR + kc * 8 + tg * 2);
            unsigned int pa[4] = { __float_as_uint(pv0.x), __float_as_uint(pv1.x),
                                   __float_as_uint(pv0.y), __float_as_uint(pv1.y) };
#pragma unroll
            for (int nt = 0; nt < 8; nt++) {
                float2 vv = *(const float2*)(Vsm + (kc * 4 + tg) * A_VSTR + (nt * 8 + gid) * 2);
                unsigned int vb[2] = { __float_as_uint(vv.x), __float_as_uint(vv.y) };
                mma8(acc[nt], pa, vb);
            }
        }
        __syncthreads();
    }

    l0 += __shfl_xor_sync(0xffffffffu, l0, 1);
    l0 += __shfl_xor_sync(0xffffffffu, l0, 2);
    l1 += __shfl_xor_sync(0xffffffffu, l1, 1);
    l1 += __shfl_xor_sync(0xffffffffu, l1, 2);
    float inv0 = 1.f / l0, inv1 = 1.f / l1;

    // epilogue: V BN-affine + hard-swish, stored tf32 col-permuted for P GEMM
    const float* aVh = aKV + h * 96 + 32;
    const float* sVh = shKV + h * 96 + 32;
    float* Ob = O + ((size_t)(b * NQ + q0)) * DHD + h * DV;
#pragma unroll
    for (int nt = 0; nt < 8; nt++) {
        int c0 = nt * 8 + 2 * tg;
        float va0 = __ldg(aVh + c0), va1 = __ldg(aVh + c0 + 1);
        float vs0 = __ldg(sVh + c0), vs1 = __ldg(sVh + c0 + 1);
        float v0 = acc[nt][0] * inv0 * va0 + vs0;
        float v1 = acc[nt][1] * inv0 * va1 + vs1;
        float v2 = acc[nt][2] * inv1 * va0 + vs0;
        float v3 = acc[nt][3] * inv1 * va1 + vs1;
        int base = nt * 8;   // 8-col group base within head slice
        float* r0p = Ob + (size_t)gid * DHD + base;
        float* r1p = Ob + (size_t)(gid + 8) * DHD + base;
        r0p[pe] = tf32f(hswish(v0)); r0p[po] = tf32f(hswish(v1));
        r1p[pe] = tf32f(hswish(v2)); r1p[po] = tf32f(hswish(v3));
    }
}

// ---------------- final BN-affine into d_out ----------------
__global__ void apply_affine_out(const float* __restrict__ Y,
                                 const float* __restrict__ a, const float* __restrict__ sh,
                                 float* __restrict__ out)
{
    int idx = blockIdx.x * blockDim.x + threadIdx.x;
    int c4 = idx & 127;
    float4 y = ((const float4*)Y)[idx];
    float4 aa = ((const float4*)a)[c4];
    float4 ss = ((const float4*)sh)[c4];
    float4 r;
    r.x = y.x * aa.x + ss.x;
    r.y = y.y * aa.y + ss.y;
    r.z = y.z * aa.z + ss.z;
    r.w = y.w * aa.w + ss.w;
    ((float4*)out)[idx] = r;
}

// ---------------- launch ----------------
extern "C" void kernel_launch(void* const* d_in, const int* in_sizes, int n_in,
                              void* d_out, int out_size)
{
    const float* x   = (const float*)d_in[0];
    const float* Wkv = (const float*)d_in[1];
    const float* gkv = (const float*)d_in[2];
    const float* bkv = (const float*)d_in[3];
    const float* Wq  = (const float*)d_in[4];
    const float* gq  = (const float*)d_in[5];
    const float* bq  = (const float*)d_in[6];
    const float* Wp  = (const float*)d_in[7];
    const float* gp  = (const float*)d_in[8];
    const float* bp  = (const float*)d_in[9];
    float* out = (float*)d_out;

    float *xp, *sXsub, *sOp, *sP, *Qt, *Kt, *Vt, *Wkvp, *Wqp, *Wpp;
    float *psKV, *pqKV, *psQ, *pqQ, *psP, *pqP;
    float *aKV, *shKV, *aQ, *shQ, *aP, *shP;
    cudaGetSymbolAddress((void**)&xp,    g_xp);
    cudaGetSymbolAddress((void**)&sXsub, g_sXsub);
    cudaGetSymbolAddress((void**)&sOp,   g_sOp);
    cudaGetSymbolAddress((void**)&sP,    g_sP);
    cudaGetSymbolAddress((void**)&Qt,    g_Qt);
    cudaGetSymbolAddress((void**)&Kt,    g_Kt);
    cudaGetSymbolAddress((void**)&Vt,    g_Vt);
    cudaGetSymbolAddress((void**)&Wkvp,  g_Wkvp);
    cudaGetSymbolAddress((void**)&Wqp,   g_Wqp);
    cudaGetSymbolAddress((void**)&Wpp,   g_Wpp);
    cudaGetSymbolAddress((void**)&psKV,  g_psumKV);
    cudaGetSymbolAddress((void**)&pqKV,  g_psqKV);
    cudaGetSymbolAddress((void**)&psQ,   g_psumQ);
    cudaGetSymbolAddress((void**)&pqQ,   g_psqQ);
    cudaGetSymbolAddress((void**)&psP,   g_psumP);
    cudaGetSymbolAddress((void**)&pqP,   g_psqP);
    cudaGetSymbolAddress((void**)&aKV,   g_aKV);
    cudaGetSymbolAddress((void**)&shKV,  g_shKV);
    cudaGetSymbolAddress((void**)&aQ,    g_aQ);
    cudaGetSymbolAddress((void**)&shQ,   g_shQ);
    cudaGetSymbolAddress((void**)&aP,    g_aP);
    cudaGetSymbolAddress((void**)&shP,   g_shP);

    static bool attr_set = false;
    if (!attr_set) {
        cudaFuncSetAttribute(attn_tc, cudaFuncAttributeMaxDynamicSharedMemorySize,
                             A_TOTALF * 4);
        cudaFuncSetAttribute(gemm_tf32_stats, cudaFuncAttributeMaxDynamicSharedMemorySize,
                             G_SMEMF * 4);
        attr_set = true;
    }

    // prep passes
    gather_q_kernel<<<(M_Q * 32) / 256, 256>>>(x, sXsub);
    permute_x<<<(M_KV * 32) / 256, 256>>>(x, xp);
    permute_w<<<(CKV * CIN + 255) / 256, 256>>>(Wkv, Wkvp, CIN, CKV * CIN);
    permute_w<<<(CQ * CIN + 255) / 256, 256>>>(Wq, Wqp, CIN, CQ * CIN);
    permute_w<<<(COUT * DHD + 255) / 256, 256>>>(Wp, Wpp, DHD, COUT * DHD);

    // projections
    gemm_tf32_stats<<<dim3(CKV / 128, M_KV / 128), 256, G_SMEMF * 4>>>(
        xp, Wkvp, Kt, Vt, psKV, pqKV, M_KV, CKV, CIN, 1);
    gemm_tf32_stats<<<dim3(CQ / 128, M_Q / 128), 256, G_SMEMF * 4>>>(
        sXsub, Wqp, Qt, nullptr, psQ, pqQ, M_Q, CQ, CIN, 2);

    // BN finalize
    bn_finalize2<<<CKV / 32, dim3(32, 16)>>>(psKV, pqKV, gkv, bkv, CKV, M_KV / 128,
                                             1.f / M_KV, aKV, shKV);
    bn_finalize2<<<CQ / 32, dim3(32, 16)>>>(psQ, pqQ, gq, bq, CQ, M_Q / 128,
                                            1.f / M_Q, aQ, shQ);

    // attention
    attn_tc<<<dim3(NQ / 64, NH, BB), 128, A_TOTALF * 4>>>(
        Qt, Kt, Vt, aQ, shQ, aKV, shKV, sOp);

    // output projection + BN
    gemm_tf32_stats<<<dim3(COUT / 128, M_Q / 128), 256, G_SMEMF * 4>>>(
        sOp, Wpp, sP, nullptr, psP, pqP, M_Q, COUT, DHD, 0);
    bn_finalize2<<<COUT / 32, dim3(32, 16)>>>(psP, pqP, gp, bp, COUT, M_Q / 128,
                                              1.f / M_Q, aP, shP);
    apply_affine_out<<<(M_Q * COUT / 4) / 256, 256>>>(sP, aP, shP, out);
}

// round 17
// speedup vs baseline: 1.2413x; 1.2413x over previous
#include <cuda_runtime.h>
#include <cuda_bf16.h>
#include <cstdint>
#include <math.h>

// ---------------- problem constants ----------------
#define BB 64
#define NTOK 1280
#define NQ 320
#define CIN 256
#define CKV 768
#define CQ 256
#define DHD 512
#define COUT 512
#define NH 8
#define KD 32
#define DV 64
#define EPSBN 1e-5f
#define SCALE_ATTN 0.17677669529663687f
#define LOG2E 1.4426950408889634f

#define M_KV (BB*NTOK)   // 81920
#define M_Q  (BB*NQ)     // 20480

// ---------------- device scratch ----------------
__device__ float g_xp[(size_t)M_KV * CIN];            // x: tf32, col-permuted
__device__ float g_sXsub[(size_t)M_Q * CIN];          // gathered x: tf32, col-permuted
__device__ float g_sOp[(size_t)M_Q * DHD];            // hswish(attn): tf32, col-permuted
__device__ float g_sP[(size_t)M_Q * COUT];
__device__ float g_Qt[(size_t)BB * NH * NQ * KD];     // raw fp32 Q head-major
__device__ float g_Kt[(size_t)BB * NH * NTOK * KD];   // tf32, col-permuted
__device__ float g_Vt[(size_t)BB * NH * NTOK * DV];   // tf32, natural head-major
__device__ float g_Wkvp[CKV * CIN];                   // tf32 permuted weights
__device__ float g_Wqp[CQ * CIN];
__device__ float g_Wpp[COUT * DHD];
__device__ float g_psumKV[640 * CKV], g_psqKV[640 * CKV];
__device__ float g_psumQ[160 * CQ],   g_psqQ[160 * CQ];
__device__ float g_psumP[160 * COUT], g_psqP[160 * COUT];
__device__ float g_aKV[CKV], g_shKV[CKV];
__device__ float g_aQ[CQ],  g_shQ[CQ];
__device__ float g_aP[COUT], g_shP[COUT];

// ---------------- helpers ----------------
__device__ __forceinline__ unsigned int f2tf(float f) {
    unsigned int r;
    asm("cvt.rna.tf32.f32 %0, %1;" : "=r"(r) : "f"(f));
    return r;
}
__device__ __forceinline__ float tf32f(float f) {
    unsigned int r;
    asm("cvt.rna.tf32.f32 %0, %1;" : "=r"(r) : "f"(f));
    return __uint_as_float(r);
}
__device__ __forceinline__ float ex2f(float x) {
    float r;
    asm("ex2.approx.f32 %0, %1;" : "=f"(r) : "f"(x));
    return r;
}
__device__ __forceinline__ int perm8i(int j) {   // k-pair (t,t+4) -> adjacent slots
    return (j < 4) ? 2 * j : 2 * (j - 4) + 1;
}
__device__ __forceinline__ void mma8(float* c, const unsigned int* a, const unsigned int* b) {
    asm volatile(
        "mma.sync.aligned.m16n8k8.row.col.f32.tf32.tf32.f32 "
        "{%0,%1,%2,%3}, {%4,%5,%6,%7}, {%8,%9}, {%0,%1,%2,%3};"
        : "+f"(c[0]), "+f"(c[1]), "+f"(c[2]), "+f"(c[3])
        : "r"(a[0]), "r"(a[1]), "r"(a[2]), "r"(a[3]), "r"(b[0]), "r"(b[1]));
}
__device__ __forceinline__ void cp_async16(unsigned int smem_addr, const void* gptr) {
    asm volatile("cp.async.cg.shared.global [%0], [%1], 16;\n"
                 :: "r"(smem_addr), "l"(gptr));
}

// permute one 8-col group: out4a=(i0,i4,i1,i5), out4b=(i2,i6,i3,i7), tf32-rounded
__device__ __forceinline__ void perm_group(const float4 a, const float4 b,
                                           float4& oa, float4& ob)
{
    oa = make_float4(tf32f(a.x), tf32f(b.x), tf32f(a.y), tf32f(b.y));
    ob = make_float4(tf32f(a.z), tf32f(b.z), tf32f(a.w), tf32f(b.w));
}

// ---------------- x -> tf32 permuted ----------------
__global__ void permute_x(const float* __restrict__ in, float* __restrict__ out)
{
    size_t g = (size_t)blockIdx.x * 256 + threadIdx.x;   // over M_KV*32 groups
    const float4* ip = (const float4*)in;
    float4* op = (float4*)out;
    float4 oa, ob;
    perm_group(ip[g * 2], ip[g * 2 + 1], oa, ob);
    op[g * 2] = oa; op[g * 2 + 1] = ob;
}

// ---------------- weight pre-permute ----------------
__global__ void permute_w(const float* __restrict__ in, float* __restrict__ out,
                          int K, int total)
{
    int i = blockIdx.x * 256 + threadIdx.x;
    if (i >= total) return;
    int row = i / K, k = i - row * K;
    int pos = (k & ~7) + perm8i(k & 7);
    out[row * K + pos] = tf32f(in[i]);
}

// ---------------- gather subsampled query tokens -> tf32 permuted ----------------
__global__ void gather_q_kernel(const float* __restrict__ x, float* __restrict__ xs)
{
    int idx = blockIdx.x * blockDim.x + threadIdx.x;   // over M_Q*32 groups
    int row = idx >> 5;
    int f   = idx & 31;          // 8-col group
    int b = row / NQ;
    int i = row - b * NQ;
    int src;
    if (i < 256) {
        int r = i >> 4, c = i & 15;
        src = (r * 2) * 32 + c * 2;
    } else {
        int j = i - 256;
        int r = j >> 3, c = j & 7;
        src = 1024 + (r * 2) * 16 + c * 2;
    }
    const float4* xp = (const float4*)x;
    float4* op = (float4*)xs;
    size_t sbase = ((size_t)b * NTOK + src) * 64 + f * 2;
    float4 oa, ob;
    perm_group(xp[sbase], xp[sbase + 1], oa, ob);
    op[(size_t)row * 64 + f * 2]     = oa;
    op[(size_t)row * 64 + f * 2 + 1] = ob;
}

// ---- tf32 GEMM: pre-permuted tf32 A and B, zero CVT, all LDS.64, stride 40 ----
// mode 0: D0 row-major MxN (P proj)   mode 1: K perm-tf32 + V tf32 head-major
// mode 2: Q raw fp32 head-major
#define GSTR 40                        // 40 ≡ 8 mod 32 -> conflict-free LDS.64
#define G_TILE (128*GSTR)              // 5120
#define G_SMEMF (4*G_TILE)             // 20480 floats = 81920 B

__global__ __launch_bounds__(256, 2)
void gemm_tf32_stats(const float* __restrict__ Ap, const float* __restrict__ Bp,
                     float* __restrict__ D0, float* __restrict__ D1,
                     float* __restrict__ psum, float* __restrict__ psq,
                     int M, int N, int K, int mode)
{
    extern __shared__ float smf[];
    unsigned int smb = (unsigned int)__cvta_generic_to_shared(smf);

    int tid = threadIdx.x;
    int bm = blockIdx.y * 128, bn = blockIdx.x * 128;
    int wid = tid >> 5, lane = tid & 31;
    int wm = (wid >> 1) << 5;
    int wn = (wid & 1) << 6;
    int gid = lane >> 2, tg = lane & 3;

    float acc[2][8][4];
#pragma unroll
    for (int im = 0; im < 2; im++)
#pragma unroll
        for (int j = 0; j < 8; j++)
#pragma unroll
            for (int r = 0; r < 4; r++) acc[im][j][r] = 0.f;

    int nch = K >> 5;
    int srow = tid >> 3, sc4 = tid & 7;

#pragma unroll
    for (int i = 0; i < 4; i++) {
        int row = srow + i * 32;
        cp_async16(smb + (unsigned int)((row * GSTR + sc4 * 4) << 2),
                   Ap + (size_t)(bm + row) * K + sc4 * 4);
        cp_async16(smb + (unsigned int)((2 * G_TILE + row * GSTR + sc4 * 4) << 2),
                   Bp + (size_t)(bn + row) * K + sc4 * 4);
    }
    asm volatile("cp.async.commit_group;\n");

    for (int c = 0; c < nch; c++) {
        if (c + 1 < nch) {
            int k0 = (c + 1) << 5;
            unsigned int aoff = ((c + 1) & 1) ? G_TILE : 0u;
            unsigned int boff = 2 * G_TILE + aoff;
#pragma unroll
            for (int i = 0; i < 4; i++) {
                int row = srow + i * 32;
                cp_async16(smb + (unsigned int)((aoff + row * GSTR + sc4 * 4) << 2),
                           Ap + (size_t)(bm + row) * K + k0 + sc4 * 4);
                cp_async16(smb + (unsigned int)((boff + row * GSTR + sc4 * 4) << 2),
                           Bp + (size_t)(bn + row) * K + k0 + sc4 * 4);
            }
            asm volatile("cp.async.commit_group;\n");
            asm volatile("cp.async.wait_group 1;\n");
        } else {
            asm volatile("cp.async.wait_group 0;\n");
        }
        __syncthreads();

        const float* Ar = smf + (c & 1) * G_TILE;
        const float* Br = smf + 2 * G_TILE + (c & 1) * G_TILE;

#pragma unroll
        for (int s = 0; s < 4; s++) {
            int kk = s * 8;
            unsigned int af[2][4], bf[8][2];
#pragma unroll
            for (int im = 0; im < 2; im++) {
                float2 v0 = *(const float2*)(Ar + (wm + im * 16 + gid) * GSTR + kk + tg * 2);
                float2 v1 = *(const float2*)(Ar + (wm + im * 16 + gid + 8) * GSTR + kk + tg * 2);
                af[im][0] = __float_as_uint(v0.x);
                af[im][1] = __float_as_uint(v1.x);
                af[im][2] = __float_as_uint(v0.y);
                af[im][3] = __float_as_uint(v1.y);
            }
#pragma unroll
            for (int j = 0; j < 8; j++) {
                float2 v = *(const float2*)(Br + (wn + j * 8 + gid) * GSTR + kk + tg * 2);
                bf[j][0] = __float_as_uint(v.x);
                bf[j][1] = __float_as_uint(v.y);
            }
#pragma unroll
            for (int im = 0; im < 2; im++)
#pragma unroll
                for (int j = 0; j < 8; j++)
                    mma8(acc[im][j], af[im], bf[j]);
        }
        __syncthreads();
    }

    // ---------- stores ----------
#pragma unroll
    for (int im = 0; im < 2; im++) {
        int r0 = bm + wm + im * 16 + gid;
#pragma unroll
        for (int j = 0; j < 8; j++) {
            int c0 = bn + wn + j * 8 + tg * 2;
            if (mode == 0) {
                *(float2*)&D0[(size_t)r0 * N + c0] = make_float2(acc[im][j][0], acc[im][j][1]);
                *(float2*)&D0[(size_t)(r0 + 8) * N + c0] = make_float2(acc[im][j][2], acc[im][j][3]);
            } else if (mode == 1) {
                int h = c0 / 96, jj = c0 % 96;
                int b = r0 / NTOK, n0 = r0 - b * NTOK;
                size_t base = ((size_t)(b * NH + h) * NTOK + n0);
                if (jj < 32) {
                    int pe = (jj & ~7) + perm8i(jj & 7);
                    int po = (jj & ~7) + perm8i((jj & 7) + 1);
                    float* kp = D0 + base * KD;
                    kp[pe] = tf32f(acc[im][j][0]);
                    kp[po] = tf32f(acc[im][j][1]);
                    kp[8 * KD + pe] = tf32f(acc[im][j][2]);
                    kp[8 * KD + po] = tf32f(acc[im][j][3]);
                } else {
                    float* vp = D1 + base * DV + (jj - 32);
                    *(float2*)vp = make_float2(tf32f(acc[im][j][0]), tf32f(acc[im][j][1]));
                    *(float2*)(vp + 8 * DV) = make_float2(tf32f(acc[im][j][2]), tf32f(acc[im][j][3]));
                }
            } else {
                int h = c0 >> 5, jj = c0 & 31;
                int b0 = r0 / NQ, q0r = r0 - b0 * NQ;
                int r1 = r0 + 8;
                int b1 = r1 / NQ, q1r = r1 - b1 * NQ;
                *(float2*)&D0[((size_t)(b0 * NH + h) * NQ + q0r) * KD + jj] =
                    make_float2(acc[im][j][0], acc[im][j][1]);
                *(float2*)&D0[((size_t)(b1 * NH + h) * NQ + q1r) * KD + jj] =
                    make_float2(acc[im][j][2], acc[im][j][3]);
            }
        }
    }

    // ---------- fused BN column stats ----------
    float cs[16], cq[16];
#pragma unroll
    for (int j = 0; j < 8; j++) {
#pragma unroll
        for (int r = 0; r < 2; r++) {
            float s = 0.f, q2 = 0.f;
#pragma unroll
            for (int im = 0; im < 2; im++) {
                float x0 = acc[im][j][r];
                float x1 = acc[im][j][r + 2];
                s += x0 + x1;
                q2 += x0 * x0 + x1 * x1;
            }
            cs[j * 2 + r] = s;
            cq[j * 2 + r] = q2;
        }
    }
#pragma unroll
    for (int m = 4; m <= 16; m <<= 1) {
#pragma unroll
        for (int i = 0; i < 16; i++) {
            cs[i] += __shfl_xor_sync(0xffffffffu, cs[i], m);
            cq[i] += __shfl_xor_sync(0xffffffffu, cq[i], m);
        }
    }
    float* st = smf;
    if (gid == 0) {
        int wmi = wid >> 1;
#pragma unroll
        for (int i = 0; i < 16; i++) {
            int cl = wn + (i >> 1) * 8 + tg * 2 + (i & 1);
            st[wmi * 128 + cl] = cs[i];
            st[512 + wmi * 128 + cl] = cq[i];
        }
    }
    __syncthreads();
    if (tid < 128) {
        float s = st[tid] + st[128 + tid] + st[256 + tid] + st[384 + tid];
        float q2 = st[512 + tid] + st[640 + tid] + st[768 + tid] + st[896 + tid];
        psum[(size_t)blockIdx.y * N + bn + tid] = s;
        psq [(size_t)blockIdx.y * N + bn + tid] = q2;
    }
}

// ---------------- BN finalize ----------------
__global__ void bn_finalize2(const float* __restrict__ psum, const float* __restrict__ psq,
                             const float* __restrict__ g, const float* __restrict__ bta,
                             int C, int R, float invM,
                             float* __restrict__ a, float* __restrict__ sh)
{
    int tx = threadIdx.x, ty = threadIdx.y;
    int col = blockIdx.x * 32 + tx;
    float s = 0.f, q2 = 0.f;
    for (int r = ty; r < R; r += 16) {
        s  += psum[(size_t)r * C + col];
        q2 += psq[(size_t)r * C + col];
    }
    __shared__ float ss[16][32], sq[16][32];
    ss[ty][tx] = s; sq[ty][tx] = q2;
    __syncthreads();
    if (ty == 0) {
        float ts = 0.f, tq = 0.f;
#pragma unroll
        for (int y = 0; y < 16; y++) { ts += ss[y][tx]; tq += sq[y][tx]; }
        float mean = ts * invM;
        float var = tq * invM - mean * mean;
        float aa = g[col] * rsqrtf(var + EPSBN);
        a[col] = aa;
        sh[col] = bta[col] - mean * aa;
    }
}

// ---------------- tensor-core flash attention (R14 layouts: K40/V72/P72) ----------------
#define SM_KSTR 40
#define SM_VSTR 72
#define SM_PSTR 72
#define SM_BUF  (64*SM_KSTR + 64*SM_VSTR)          // 7168 floats
#define SM_POFF (2*SM_BUF)                          // 14336
#define SM_TOTALF (SM_POFF + 4 * 16 * SM_PSTR)      // 18944 floats = 75776 B

__device__ __forceinline__ void stage_tile(unsigned int smem_bytes,
                                           const float* __restrict__ Kg,
                                           const float* __restrict__ Vg,
                                           int kt, int tid)
{
    const float4* Ks = (const float4*)(Kg + (size_t)kt * 64 * KD);
    const float4* Vs = (const float4*)(Vg + (size_t)kt * 64 * DV);
#pragma unroll
    for (int i = 0; i < 4; i++) {
        int idx = i * 128 + tid; int r = idx >> 3, f = idx & 7;
        cp_async16(smem_bytes + (unsigned int)((r * SM_KSTR + f * 4) << 2), Ks + r * 8 + f);
    }
#pragma unroll
    for (int i = 0; i < 8; i++) {
        int idx = i * 128 + tid; int r = idx >> 4, f = idx & 15;
        cp_async16(smem_bytes + (unsigned int)((64 * SM_KSTR + r * SM_VSTR + f * 4) << 2),
                   Vs + r * 16 + f);
    }
}

__device__ __forceinline__ float hswish(float x) {
    return x * fminf(fmaxf(x + 3.f, 0.f), 6.f) * (1.f / 6.f);
}

__global__ __launch_bounds__(128)
void attn_tc(const float* __restrict__ Qt, const float* __restrict__ Kt,
             const float* __restrict__ Vt,
             const float* __restrict__ aQ, const float* __restrict__ shQ,
             const float* __restrict__ aKV, const float* __restrict__ shKV,
             float* __restrict__ O)
{
    extern __shared__ float smf[];
    int tid  = threadIdx.x;
    int warp = tid >> 5, lane = tid & 31;
    int gid = lane >> 2, tg = lane & 3;
    int qt = blockIdx.x, h = blockIdx.y, b = blockIdx.z;
    int bh = b * NH + h;

    const float* Kg = Kt + (size_t)bh * NTOK * KD;
    const float* Vg = Vt + (size_t)bh * NTOK * DV;
    unsigned int smb = (unsigned int)__cvta_generic_to_shared(smf);
    float* Pw = smf + SM_POFF + warp * (16 * SM_PSTR);

    int q0 = qt * 64 + warp * 16;
    const float* Qg  = Qt + ((size_t)bh * NQ + q0) * KD;
    const float* aQh = aQ + h * KD;
    const float* sQh = shQ + h * KD;
    const float* aKh = aKV + h * 96;
    const float SC = SCALE_ATTN * LOG2E;
    unsigned int qa[4][4];
#pragma unroll
    for (int kc = 0; kc < 4; kc++) {
        int c0 = kc * 8 + tg, c1 = c0 + 4;
        float m0 = __ldg(aQh + c0) * __ldg(aKh + c0) * SC;
        float o0 = __ldg(sQh + c0) * __ldg(aKh + c0) * SC;
        float m1 = __ldg(aQh + c1) * __ldg(aKh + c1) * SC;
        float o1 = __ldg(sQh + c1) * __ldg(aKh + c1) * SC;
        qa[kc][0] = f2tf(__ldg(Qg + gid * KD + c0)       * m0 + o0);
        qa[kc][1] = f2tf(__ldg(Qg + (gid + 8) * KD + c0) * m0 + o0);
        qa[kc][2] = f2tf(__ldg(Qg + gid * KD + c1)       * m1 + o1);
        qa[kc][3] = f2tf(__ldg(Qg + (gid + 8) * KD + c1) * m1 + o1);
    }

    float acc[8][4];
#pragma unroll
    for (int nt = 0; nt < 8; nt++)
#pragma unroll
        for (int r = 0; r < 4; r++) acc[nt][r] = 0.f;
    float l0 = 0.f, l1 = 0.f;

    int pe = perm8i(2 * tg), po = perm8i(2 * tg + 1);

    stage_tile(smb, Kg, Vg, 0, tid);
    asm volatile("cp.async.commit_group;\n");

    const int NKT = NTOK / 64;
    for (int kt = 0; kt < NKT; kt++) {
        if (kt + 1 < NKT) {
            stage_tile(smb + ((kt + 1) & 1) * SM_BUF * 4, Kg, Vg, kt + 1, tid);
            asm volatile("cp.async.commit_group;\n");
            asm volatile("cp.async.wait_group 1;\n");
        } else {
            asm volatile("cp.async.wait_group 0;\n");
        }
        __syncthreads();

        const float* Ksm = smf + (kt & 1) * SM_BUF;
        const float* Vsm = Ksm + 64 * SM_KSTR;

#pragma unroll
        for (int nt = 0; nt < 8; nt++) {
            float c[4] = {0.f, 0.f, 0.f, 0.f};
#pragma unroll
            for (int kc = 0; kc < 4; kc++) {
                float2 kv = *(const float2*)(Ksm + (nt * 8 + gid) * SM_KSTR + kc * 8 + tg * 2);
                unsigned int bb[2] = { __float_as_uint(kv.x), __float_as_uint(kv.y) };
                mma8(c, qa[kc], bb);
            }
            float p0 = ex2f(c[0]), p1 = ex2f(c[1]);
            float p2 = ex2f(c[2]), p3 = ex2f(c[3]);
            l0 += p0 + p1;
            l1 += p2 + p3;
            float* pr0 = Pw + gid * SM_PSTR + nt * 8;
            float* pr1 = Pw + (gid + 8) * SM_PSTR + nt * 8;
            pr0[pe] = tf32f(p0); pr0[po] = tf32f(p1);
            pr1[pe] = tf32f(p2); pr1[po] = tf32f(p3);
        }
        __syncwarp();

#pragma unroll
        for (int kc = 0; kc < 8; kc++) {
            float2 pv0 = *(const float2*)(Pw + gid * SM_PSTR + kc * 8 + tg * 2);
            float2 pv1 = *(const float2*)(Pw + (gid + 8) * SM_PSTR + kc * 8 + tg * 2);
            unsigned int pa[4] = { __float_as_uint(pv0.x), __float_as_uint(pv1.x),
                                   __float_as_uint(pv0.y), __float_as_uint(pv1.y) };
#pragma unroll
            for (int nt = 0; nt < 8; nt++) {
                const float* vp = Vsm + (kc * 8 + tg) * SM_VSTR + nt * 8 + gid;
                unsigned int vb[2] = { __float_as_uint(vp[0]),
                                       __float_as_uint(vp[4 * SM_VSTR]) };
                mma8(acc[nt], pa, vb);
            }
        }
        __syncthreads();
    }

    l0 += __shfl_xor_sync(0xffffffffu, l0, 1);
    l0 += __shfl_xor_sync(0xffffffffu, l0, 2);
    l1 += __shfl_xor_sync(0xffffffffu, l1, 1);
    l1 += __shfl_xor_sync(0xffffffffu, l1, 2);
    float inv0 = 1.f / l0, inv1 = 1.f / l1;

    // epilogue: V BN-affine + hard-swish, stored tf32 col-permuted for P GEMM
    const float* aVh = aKV + h * 96 + 32;
    const float* sVh = shKV + h * 96 + 32;
    float* Ob = O + ((size_t)(b * NQ + q0)) * DHD + h * DV;
#pragma unroll
    for (int nt = 0; nt < 8; nt++) {
        int c0 = nt * 8 + 2 * tg;
        float va0 = __ldg(aVh + c0), va1 = __ldg(aVh + c0 + 1);
        float vs0 = __ldg(sVh + c0), vs1 = __ldg(sVh + c0 + 1);
        float v0 = acc[nt][0] * inv0 * va0 + vs0;
        float v1 = acc[nt][1] * inv0 * va1 + vs1;
        float v2 = acc[nt][2] * inv1 * va0 + vs0;
        float v3 = acc[nt][3] * inv1 * va1 + vs1;
        int base = nt * 8;
        float* r0p = Ob + (size_t)gid * DHD + base;
        float* r1p = Ob + (size_t)(gid + 8) * DHD + base;
        r0p[pe] = tf32f(hswish(v0)); r0p[po] = tf32f(hswish(v1));
        r1p[pe] = tf32f(hswish(v2)); r1p[po] = tf32f(hswish(v3));
    }
}

// ---------------- final BN-affine into d_out ----------------
__global__ void apply_affine_out(const float* __restrict__ Y,
                                 const float* __restrict__ a, const float* __restrict__ sh,
                                 float* __restrict__ out)
{
    int idx = blockIdx.x * blockDim.x + threadIdx.x;
    int c4 = idx & 127;
    float4 y = ((const float4*)Y)[idx];
    float4 aa = ((const float4*)a)[c4];
    float4 ss = ((const float4*)sh)[c4];
    float4 r;
    r.x = y.x * aa.x + ss.x;
    r.y = y.y * aa.y + ss.y;
    r.z = y.z * aa.z + ss.z;
    r.w = y.w * aa.w + ss.w;
    ((float4*)out)[idx] = r;
}

// ---------------- launch ----------------
extern "C" void kernel_launch(void* const* d_in, const int* in_sizes, int n_in,
                              void* d_out, int out_size)
{
    const float* x   = (const float*)d_in[0];
    const float* Wkv = (const float*)d_in[1];
    const float* gkv = (const float*)d_in[2];
    const float* bkv = (const float*)d_in[3];
    const float* Wq  = (const float*)d_in[4];
    const float* gq  = (const float*)d_in[5];
    const float* bq  = (const float*)d_in[6];
    const float* Wp  = (const float*)d_in[7];
    const float* gp  = (const float*)d_in[8];
    const float* bp  = (const float*)d_in[9];
    float* out = (float*)d_out;

    float *xp, *sXsub, *sOp, *sP, *Qt, *Kt, *Vt, *Wkvp, *Wqp, *Wpp;
    float *psKV, *pqKV, *psQ, *pqQ, *psP, *pqP;
    float *aKV, *shKV, *aQ, *shQ, *aP, *shP;
    cudaGetSymbolAddress((void**)&xp,    g_xp);
    cudaGetSymbolAddress((void**)&sXsub, g_sXsub);
    cudaGetSymbolAddress((void**)&sOp,   g_sOp);
    cudaGetSymbolAddress((void**)&sP,    g_sP);
    cudaGetSymbolAddress((void**)&Qt,    g_Qt);
    cudaGetSymbolAddress((void**)&Kt,    g_Kt);
    cudaGetSymbolAddress((void**)&Vt,    g_Vt);
    cudaGetSymbolAddress((void**)&Wkvp,  g_Wkvp);
    cudaGetSymbolAddress((void**)&Wqp,   g_Wqp);
    cudaGetSymbolAddress((void**)&Wpp,   g_Wpp);
    cudaGetSymbolAddress((void**)&psKV,  g_psumKV);
    cudaGetSymbolAddress((void**)&pqKV,  g_psqKV);
    cudaGetSymbolAddress((void**)&psQ,   g_psumQ);
    cudaGetSymbolAddress((void**)&pqQ,   g_psqQ);
    cudaGetSymbolAddress((void**)&psP,   g_psumP);
    cudaGetSymbolAddress((void**)&pqP,   g_psqP);
    cudaGetSymbolAddress((void**)&aKV,   g_aKV);
    cudaGetSymbolAddress((void**)&shKV,  g_shKV);
    cudaGetSymbolAddress((void**)&aQ,    g_aQ);
    cudaGetSymbolAddress((void**)&shQ,   g_shQ);
    cudaGetSymbolAddress((void**)&aP,    g_aP);
    cudaGetSymbolAddress((void**)&shP,   g_shP);

    static bool attr_set = false;
    if (!attr_set) {
        cudaFuncSetAttribute(attn_tc, cudaFuncAttributeMaxDynamicSharedMemorySize,
                             SM_TOTALF * 4);
        cudaFuncSetAttribute(gemm_tf32_stats, cudaFuncAttributeMaxDynamicSharedMemorySize,
                             G_SMEMF * 4);
        attr_set = true;
    }

    // prep passes (KV GEMM lands at ncu's -s 5 slot)
    gather_q_kernel<<<(M_Q * 32) / 256, 256>>>(x, sXsub);
    permute_x<<<(M_KV * 32) / 256, 256>>>(x, xp);
    permute_w<<<(CKV * CIN + 255) / 256, 256>>>(Wkv, Wkvp, CIN, CKV * CIN);
    permute_w<<<(CQ * CIN + 255) / 256, 256>>>(Wq, Wqp, CIN, CQ * CIN);
    permute_w<<<(COUT * DHD + 255) / 256, 256>>>(Wp, Wpp, DHD, COUT * DHD);

    // projections
    gemm_tf32_stats<<<dim3(CKV / 128, M_KV / 128), 256, G_SMEMF * 4>>>(
        xp, Wkvp, Kt, Vt, psKV, pqKV, M_KV, CKV, CIN, 1);
    gemm_tf32_stats<<<dim3(CQ / 128, M_Q / 128), 256, G_SMEMF * 4>>>(
        sXsub, Wqp, Qt, nullptr, psQ, pqQ, M_Q, CQ, CIN, 2);

    // BN finalize
    bn_finalize2<<<CKV / 32, dim3(32, 16)>>>(psKV, pqKV, gkv, bkv, CKV, M_KV / 128,
                                             1.f / M_KV, aKV, shKV);
    bn_finalize2<<<CQ / 32, dim3(32, 16)>>>(psQ, pqQ, gq, bq, CQ, M_Q / 128,
                                            1.f / M_Q, aQ, shQ);

    // attention
    attn_tc<<<dim3(NQ / 64, NH, BB), 128, SM_TOTALF * 4>>>(
        Qt, Kt, Vt, aQ, shQ, aKV, shKV, sOp);

    // output projection + BN
    gemm_tf32_stats<<<dim3(COUT / 128, M_Q / 128), 256, G_SMEMF * 4>>>(
        sOp, Wpp, sP, nullptr, psP, pqP, M_Q, COUT, DHD, 0);
    bn_finalize2<<<COUT / 32, dim3(32, 16)>>>(psP, pqP, gp, bp, COUT, M_Q / 128,
                                              1.f / M_Q, aP, shP);
    apply_affine_out<<<(M_Q * COUT / 4) / 256, 256>>>(sP, aP, shP, out);
}